// round 3
// baseline (speedup 1.0000x reference)
#include <cuda_runtime.h>
#include <cuda_bf16.h>

// Problem constants (fixed by the reference)
#define WF 512.0f
#define HF 512.0f
#define NG 2048
#define NPAIR (NG / 2)
#define TPB 512

// Packed per-pair coefficients: for pair p (gaussians 2p, 2p+1):
// [P0,P1, Q0,Q1, R0,R1, NMX0,NMX1, NMY0,NMY1, CR0,CR1, CG0,CG1, CB0,CB1]
// P,Q,R already scaled by -log2(e); NMX/NMY = -mu in pixel units.
__device__ float g_coef[NPAIR * 16];

typedef unsigned long long u64;

__device__ __forceinline__ u64 f2add(u64 a, u64 b) {
    u64 r; asm("add.rn.f32x2 %0,%1,%2;" : "=l"(r) : "l"(a), "l"(b)); return r;
}
__device__ __forceinline__ u64 f2mul(u64 a, u64 b) {
    u64 r; asm("mul.rn.f32x2 %0,%1,%2;" : "=l"(r) : "l"(a), "l"(b)); return r;
}
__device__ __forceinline__ u64 f2fma(u64 a, u64 b, u64 c) {
    u64 r; asm("fma.rn.f32x2 %0,%1,%2,%3;" : "=l"(r) : "l"(a), "l"(b), "l"(c)); return r;
}
__device__ __forceinline__ u64 pk(float lo, float hi) {
    u64 r; asm("mov.b64 %0,{%1,%2};" : "=l"(r) : "f"(lo), "f"(hi)); return r;
}
__device__ __forceinline__ float2 upk(u64 v) {
    float2 o; asm("mov.b64 {%0,%1},%2;" : "=f"(o.x), "=f"(o.y) : "l"(v)); return o;
}
__device__ __forceinline__ float ex2(float x) {
    float r; asm("ex2.approx.ftz.f32 %0,%1;" : "=f"(r) : "f"(x)); return r;
}

// ---------------------------------------------------------------------------
// Precompute kernel: N gaussians -> packed quadratic coefficients + colors.
// All transcendentals (tanh/sin/cos/sigmoid) happen here ONCE per gaussian.
// ---------------------------------------------------------------------------
__global__ void precompute_kernel(const float* __restrict__ rgb,
                                  const float* __restrict__ mu,
                                  const float* __restrict__ scale,
                                  const float* __restrict__ angle,
                                  int n) {
    int i = blockIdx.x * blockDim.x + threadIdx.x;
    if (i >= n) return;

    const float MU_BORDER = 1.05f;
    const float PI_APPROX = 3.1416f;
    const float S_MIN = 1.0f / 30.0f;
    const float S_MAX = 1.0f / 0.75f;
    const float LOG2E = 1.4426950408889634f;

    // mu in pixel units: vec = x_px - (tanh(mu)*1.05 + 1) * 0.5 * wh
    float mpx = (tanhf(mu[2 * i + 0]) * MU_BORDER + 1.0f) * 0.5f * WF;
    float mpy = (tanhf(mu[2 * i + 1]) * MU_BORDER + 1.0f) * 0.5f * HF;

    float al = tanhf(angle[i]) * PI_APPROX;
    float c = cosf(al);
    float s = sinf(al);

    float S0 = 1.0f / (1.0f + expf(-scale[2 * i + 0])) * (S_MAX - S_MIN) + S_MIN;
    float S1 = 1.0f / (1.0f + expf(-scale[2 * i + 1])) * (S_MAX - S_MIN) + S_MIN;

    // d1x = S0*(c*vx - s*vy), d1y = S1*(s*vx + c*vy)
    float a = S0 * c, b = -S0 * s;
    float e = S1 * s, f = S1 * c;

    // q = d1x^2 + d1y^2 = P vx^2 + Q vx vy + R vy^2 ; fold -log2(e) for ex2
    float P = -LOG2E * (a * a + e * e);
    float Q = -LOG2E * 2.0f * (a * b + e * f);
    float R = -LOG2E * (b * b + f * f);

    float cr = 1.0f / (1.0f + expf(-rgb[3 * i + 0]));
    float cg = 1.0f / (1.0f + expf(-rgb[3 * i + 1]));
    float cb = 1.0f / (1.0f + expf(-rgb[3 * i + 2]));

    int p = i >> 1;
    int l = i & 1;
    float* base = g_coef + p * 16;
    base[0 + l]  = P;
    base[2 + l]  = Q;
    base[4 + l]  = R;
    base[6 + l]  = -mpx;
    base[8 + l]  = -mpy;
    base[10 + l] = cr;
    base[12 + l] = cg;
    base[14 + l] = cb;
}

// ---------------------------------------------------------------------------
// Main splat kernel: 1 pixel / thread, TPB=512, grid=B/512=128 blocks.
// Exactly 1 block/SM on 128 of 148 SMs -> 4 warps/SMSP for latency hiding.
// Full 64KB coefficient table resident in smem; single sync; unroll 8.
// ---------------------------------------------------------------------------
__global__ void __launch_bounds__(TPB, 1) splat_kernel(const float* __restrict__ x,
                                                       float* __restrict__ out,
                                                       int B) {
    __shared__ float sc[NPAIR * 16];  // 64 KB, all 1024 pairs

    int pix = blockIdx.x * TPB + threadIdx.x;
    bool valid = pix < B;

    float px = 0.0f, py = 0.0f;
    if (valid) {
        float2 xy = ((const float2*)x)[pix];
        px = xy.x; py = xy.y;
    }
    u64 px2 = pk(px, px);
    u64 py2 = pk(py, py);

    // Cooperative load of the whole table: 4096 float4 / 512 threads = 8 each
    {
        const float4* gsrc = (const float4*)g_coef;
        float4* dst = (float4*)sc;
#pragma unroll
        for (int i = 0; i < (NPAIR * 16 / 4) / TPB; i++) {
            dst[threadIdx.x + i * TPB] = gsrc[threadIdx.x + i * TPB];
        }
    }
    __syncthreads();

    u64 aR = 0ull, aG = 0ull, aB = 0ull;  // packed (lo,hi) accumulators

#pragma unroll 8
    for (int p = 0; p < NPAIR; p++) {
        const ulonglong2* sp = (const ulonglong2*)(sc + p * 16);
        ulonglong2 c01 = sp[0];   // {P2, Q2}
        ulonglong2 c23 = sp[1];   // {R2, NMX2}
        ulonglong2 c45 = sp[2];   // {NMY2, CR2}
        ulonglong2 c67 = sp[3];   // {CG2, CB2}

        u64 vx = f2add(px2, c23.y);                  // x - mx
        u64 vy = f2add(py2, c45.x);                  // y - my
        u64 t1 = f2fma(c01.y, vy, f2mul(c01.x, vx)); // P*vx + Q*vy
        u64 q  = f2fma(vx, t1, f2mul(f2mul(c23.x, vy), vy)); // + R*vy^2

        float2 qq = upk(q);
        u64 w = pk(ex2(qq.x), ex2(qq.y));

        aR = f2fma(w, c45.y, aR);
        aG = f2fma(w, c67.x, aG);
        aB = f2fma(w, c67.y, aB);
    }

    if (valid) {
        float2 r = upk(aR), g = upk(aG), b = upk(aB);
        out[3 * pix + 0] = r.x + r.y;
        out[3 * pix + 1] = g.x + g.y;
        out[3 * pix + 2] = b.x + b.y;
    }
}

// ---------------------------------------------------------------------------
// Launch: inputs in metadata order: x[B,2], rgb[N,3], mu[N,2], scale[N,2], angle[N]
// ---------------------------------------------------------------------------
extern "C" void kernel_launch(void* const* d_in, const int* in_sizes, int n_in,
                              void* d_out, int out_size) {
    const float* x     = (const float*)d_in[0];
    const float* rgb   = (const float*)d_in[1];
    const float* mu    = (const float*)d_in[2];
    const float* scale = (const float*)d_in[3];
    const float* angle = (const float*)d_in[4];
    float* out = (float*)d_out;

    int N = in_sizes[4];          // 2048
    int B = in_sizes[0] / 2;      // 65536

    precompute_kernel<<<(N + 255) / 256, 256>>>(rgb, mu, scale, angle, N);

    int blocks = (B + TPB - 1) / TPB;   // 128
    splat_kernel<<<blocks, TPB>>>(x, out, B);
}

// round 4
// speedup vs baseline: 1.1858x; 1.1858x over previous
#include <cuda_runtime.h>
#include <cuda_bf16.h>

// Problem constants (fixed by the reference)
#define WF 512.0f
#define HF 512.0f
#define NG 2048
#define NPAIR (NG / 2)          // 1024 gaussian pairs
#define HALF_PAIRS (NPAIR / 2)  // 512 pairs per gaussian-half
#define TPB 448                 // 14 warps/block -> 3.5 warps/SMSP
#define BMAX 65536

// Packed per-pair coefficients: for pair p (gaussians 2p, 2p+1):
// [P0,P1, Q0,Q1, R0,R1, NMX0,NMX1, NMY0,NMY1, CR0,CR1, CG0,CG1, CB0,CB1]
// P,Q,R already scaled by -log2(e); NMX/NMY = -mu in pixel units.
__device__ float g_coef[NPAIR * 16];
// Partial images for the two gaussian halves (split-N accumulation, no atomics)
__device__ float g_partial[2][BMAX * 3];

typedef unsigned long long u64;

__device__ __forceinline__ u64 f2add(u64 a, u64 b) {
    u64 r; asm("add.rn.f32x2 %0,%1,%2;" : "=l"(r) : "l"(a), "l"(b)); return r;
}
__device__ __forceinline__ u64 f2mul(u64 a, u64 b) {
    u64 r; asm("mul.rn.f32x2 %0,%1,%2;" : "=l"(r) : "l"(a), "l"(b)); return r;
}
__device__ __forceinline__ u64 f2fma(u64 a, u64 b, u64 c) {
    u64 r; asm("fma.rn.f32x2 %0,%1,%2,%3;" : "=l"(r) : "l"(a), "l"(b), "l"(c)); return r;
}
__device__ __forceinline__ u64 pk(float lo, float hi) {
    u64 r; asm("mov.b64 %0,{%1,%2};" : "=l"(r) : "f"(lo), "f"(hi)); return r;
}
__device__ __forceinline__ float2 upk(u64 v) {
    float2 o; asm("mov.b64 {%0,%1},%2;" : "=f"(o.x), "=f"(o.y) : "l"(v)); return o;
}
__device__ __forceinline__ float ex2(float x) {
    float r; asm("ex2.approx.ftz.f32 %0,%1;" : "=f"(r) : "f"(x)); return r;
}

// ---------------------------------------------------------------------------
// Precompute kernel: N gaussians -> packed quadratic coefficients + colors.
// ---------------------------------------------------------------------------
__global__ void precompute_kernel(const float* __restrict__ rgb,
                                  const float* __restrict__ mu,
                                  const float* __restrict__ scale,
                                  const float* __restrict__ angle,
                                  int n) {
    int i = blockIdx.x * blockDim.x + threadIdx.x;
    if (i >= n) return;

    const float MU_BORDER = 1.05f;
    const float PI_APPROX = 3.1416f;
    const float S_MIN = 1.0f / 30.0f;
    const float S_MAX = 1.0f / 0.75f;
    const float LOG2E = 1.4426950408889634f;

    float mpx = (tanhf(mu[2 * i + 0]) * MU_BORDER + 1.0f) * 0.5f * WF;
    float mpy = (tanhf(mu[2 * i + 1]) * MU_BORDER + 1.0f) * 0.5f * HF;

    float al = tanhf(angle[i]) * PI_APPROX;
    float c = cosf(al);
    float s = sinf(al);

    float S0 = 1.0f / (1.0f + expf(-scale[2 * i + 0])) * (S_MAX - S_MIN) + S_MIN;
    float S1 = 1.0f / (1.0f + expf(-scale[2 * i + 1])) * (S_MAX - S_MIN) + S_MIN;

    float a = S0 * c, b = -S0 * s;
    float e = S1 * s, f = S1 * c;

    float P = -LOG2E * (a * a + e * e);
    float Q = -LOG2E * 2.0f * (a * b + e * f);
    float R = -LOG2E * (b * b + f * f);

    float cr = 1.0f / (1.0f + expf(-rgb[3 * i + 0]));
    float cg = 1.0f / (1.0f + expf(-rgb[3 * i + 1]));
    float cb = 1.0f / (1.0f + expf(-rgb[3 * i + 2]));

    int p = i >> 1;
    int l = i & 1;
    float* base = g_coef + p * 16;
    base[0 + l]  = P;
    base[2 + l]  = Q;
    base[4 + l]  = R;
    base[6 + l]  = -mpx;
    base[8 + l]  = -mpy;
    base[10 + l] = cr;
    base[12 + l] = cg;
    base[14 + l] = cb;
}

// ---------------------------------------------------------------------------
// Splat kernel: split-N over 2 gaussian halves. grid = 148 blocks exactly.
// Block b: half = b&1, covers pixels [2t, 2t+1] for t = (b>>1)*TPB + tid.
// 2 px/thread amortizes the 64B/pair LDS over 2x the FMA work; software
// pipeline (prefetch next pair) hides LDS latency.
// ---------------------------------------------------------------------------
__global__ void __launch_bounds__(TPB, 1) splat_kernel(const float* __restrict__ x,
                                                       int B) {
    __shared__ float sc[HALF_PAIRS * 16 + 16];  // 32KB + 1 pad pair

    int h  = blockIdx.x & 1;
    int tb = blockIdx.x >> 1;
    int t  = tb * TPB + threadIdx.x;
    int pA = 2 * t;
    bool valid = pA + 1 < B;

    // cooperative tile load of this half's 512 pairs (+1 pad pair = wrap)
    {
        const float4* gsrc = (const float4*)(g_coef + h * HALF_PAIRS * 16);
        float4* dst = (float4*)sc;
        for (int i = threadIdx.x; i < HALF_PAIRS * 4; i += TPB) dst[i] = gsrc[i];
        if (threadIdx.x < 4) dst[HALF_PAIRS * 4 + threadIdx.x] = gsrc[threadIdx.x];
    }
    __syncthreads();

    float4 xy = make_float4(0.f, 0.f, 0.f, 0.f);
    if (valid) xy = ((const float4*)x)[t];   // pixels 2t and 2t+1

    u64 xA = pk(xy.x, xy.x), yA = pk(xy.y, xy.y);
    u64 xB = pk(xy.z, xy.z), yB = pk(xy.w, xy.w);

    u64 aR = 0ull, aG = 0ull, aB = 0ull;
    u64 bR = 0ull, bG = 0ull, bB = 0ull;

    const ulonglong2* sp = (const ulonglong2*)sc;
    ulonglong2 c0 = sp[0], c1 = sp[1], c2 = sp[2], c3 = sp[3];

#pragma unroll 4
    for (int p = 0; p < HALF_PAIRS; p++) {
        // prefetch next pair's coefficients (pad pair makes last read safe)
        ulonglong2 d0 = sp[4 * p + 4];
        ulonglong2 d1 = sp[4 * p + 5];
        ulonglong2 d2 = sp[4 * p + 6];
        ulonglong2 d3 = sp[4 * p + 7];

        // ---- pixel A ----
        {
            u64 vx = f2add(xA, c1.y);
            u64 vy = f2add(yA, c2.x);
            u64 t1 = f2fma(c0.y, vy, f2mul(c0.x, vx));            // P*vx + Q*vy
            u64 q  = f2fma(vx, t1, f2mul(f2mul(c1.x, vy), vy));   // + R*vy^2
            float2 qq = upk(q);
            u64 w = pk(ex2(qq.x), ex2(qq.y));
            aR = f2fma(w, c2.y, aR);
            aG = f2fma(w, c3.x, aG);
            aB = f2fma(w, c3.y, aB);
        }
        // ---- pixel B ----
        {
            u64 vx = f2add(xB, c1.y);
            u64 vy = f2add(yB, c2.x);
            u64 t1 = f2fma(c0.y, vy, f2mul(c0.x, vx));
            u64 q  = f2fma(vx, t1, f2mul(f2mul(c1.x, vy), vy));
            float2 qq = upk(q);
            u64 w = pk(ex2(qq.x), ex2(qq.y));
            bR = f2fma(w, c2.y, bR);
            bG = f2fma(w, c3.x, bG);
            bB = f2fma(w, c3.y, bB);
        }

        c0 = d0; c1 = d1; c2 = d2; c3 = d3;
    }

    if (valid) {
        float* o = &g_partial[h][pA * 3];   // 6 consecutive floats, 8B aligned
        float2 r0 = upk(aR), g0 = upk(aG), b0 = upk(aB);
        float2 r1 = upk(bR), g1 = upk(bG), b1 = upk(bB);
        float2 s01 = make_float2(r0.x + r0.y, g0.x + g0.y);
        float2 s23 = make_float2(b0.x + b0.y, r1.x + r1.y);
        float2 s45 = make_float2(g1.x + g1.y, b1.x + b1.y);
        ((float2*)o)[0] = s01;
        ((float2*)o)[1] = s23;
        ((float2*)o)[2] = s45;
    }
}

// ---------------------------------------------------------------------------
// Combine the two partial images into d_out.
// ---------------------------------------------------------------------------
__global__ void combine_kernel(float* __restrict__ out, int n4) {
    int i = blockIdx.x * blockDim.x + threadIdx.x;
    if (i < n4) {
        float4 a = ((const float4*)g_partial[0])[i];
        float4 b = ((const float4*)g_partial[1])[i];
        float4 s;
        s.x = a.x + b.x; s.y = a.y + b.y; s.z = a.z + b.z; s.w = a.w + b.w;
        ((float4*)out)[i] = s;
    }
}

// ---------------------------------------------------------------------------
// Launch: inputs in metadata order: x[B,2], rgb[N,3], mu[N,2], scale[N,2], angle[N]
// ---------------------------------------------------------------------------
extern "C" void kernel_launch(void* const* d_in, const int* in_sizes, int n_in,
                              void* d_out, int out_size) {
    const float* x     = (const float*)d_in[0];
    const float* rgb   = (const float*)d_in[1];
    const float* mu    = (const float*)d_in[2];
    const float* scale = (const float*)d_in[3];
    const float* angle = (const float*)d_in[4];
    float* out = (float*)d_out;

    int N = in_sizes[4];          // 2048
    int B = in_sizes[0] / 2;      // 65536

    precompute_kernel<<<(N + 255) / 256, 256>>>(rgb, mu, scale, angle, N);

    // 2 gaussian-halves x ceil((B/2)/TPB) pixel-blocks = 148 blocks total
    int pix_blocks = (B / 2 + TPB - 1) / TPB;   // 74
    splat_kernel<<<pix_blocks * 2, TPB>>>(x, B);

    int n4 = (B * 3) / 4;                        // 49152 float4
    combine_kernel<<<(n4 + 255) / 256, 256>>>(out, n4);
}